// round 2
// baseline (speedup 1.0000x reference)
#include <cuda_runtime.h>

// Problem shapes (fixed by the dataset)
#define DD   1024
#define BSZ  2
#define LSEQ 2048
#define NST  16
#define MROWS (BSZ*LSEQ)      // 4096
#define NCHUNK 32
#define CLEN  (LSEQ/NCHUNK)   // 64

// ---------------- scratch (no allocs allowed) ----------------
__device__ float g_z [MROWS*DD];
__device__ float g_xs[MROWS*DD];
__device__ float g_dt[MROWS*DD];
__device__ float g_Bm[MROWS*NST];
__device__ float g_Cc[MROWS*NST];
__device__ float g_u [MROWS*DD];
__device__ float g_hend[BSZ*DD*NCHUNK*NST];
__device__ float g_P   [BSZ*DD*NCHUNK*NST];
__device__ float g_hs  [BSZ*DD*NCHUNK*NST];

// ---------------- helpers ----------------
__device__ __forceinline__ float2 ffma2(float2 a, float2 b, float2 c) {
    // Blackwell packed fp32 FMA (FFMA2) — 2 fp32 FMA per instruction.
    asm("{\n\t"
        ".reg .b64 ra, rb, rc;\n\t"
        "mov.b64 ra, {%2,%3};\n\t"
        "mov.b64 rb, {%4,%5};\n\t"
        "mov.b64 rc, {%6,%7};\n\t"
        "fma.rn.f32x2 rc, ra, rb, rc;\n\t"
        "mov.b64 {%0,%1}, rc;\n\t"
        "}"
        : "=f"(c.x), "=f"(c.y)
        : "f"(a.x), "f"(a.y), "f"(b.x), "f"(b.y), "f"(c.x), "f"(c.y));
    return c;
}

__device__ __forceinline__ float act_sigmoid(float x) {
    return 1.0f / (1.0f + __expf(-x));
}
__device__ __forceinline__ float act_softplus(float x) {
    // logaddexp(x, 0) — matches jax.nn.softplus
    return fmaxf(x, 0.0f) + log1pf(__expf(-fabsf(x)));
}

// ---------------- fp32 GEMM core: out = act(A @ W + bias) ----------------
// A: M x K row-major, W: K x N row-major, out: M x N row-major
// 128x128x16 tiles, 256 threads, 8x8 per thread, FFMA2 inner product.
// Double-buffered shared tiles: one barrier per K-slice, loads overlapped.
#define BM 128
#define BN 128
#define BK 16
#define TM 8
#define TN 8

struct GemmSmem {
    float As[2][BK][BM + 4];
    float Bs[2][BK][BN];
};

__device__ __forceinline__
void gemm_load_tile(GemmSmem& s, int buf,
                    const float* __restrict__ A, const float* __restrict__ W,
                    int bm, int bn, int kk, int K, int N,
                    int ar, int ac, int br, int bc)
{
    float4 a0 = *reinterpret_cast<const float4*>(&A[(size_t)(bm + ar) * K + kk + ac]);
    float4 a1 = *reinterpret_cast<const float4*>(&A[(size_t)(bm + ar + 64) * K + kk + ac]);
    s.As[buf][ac + 0][ar] = a0.x; s.As[buf][ac + 1][ar] = a0.y;
    s.As[buf][ac + 2][ar] = a0.z; s.As[buf][ac + 3][ar] = a0.w;
    s.As[buf][ac + 0][ar + 64] = a1.x; s.As[buf][ac + 1][ar + 64] = a1.y;
    s.As[buf][ac + 2][ar + 64] = a1.z; s.As[buf][ac + 3][ar + 64] = a1.w;
    *reinterpret_cast<float4*>(&s.Bs[buf][br][bc]) =
        *reinterpret_cast<const float4*>(&W[(size_t)(kk + br) * N + bn + bc]);
    *reinterpret_cast<float4*>(&s.Bs[buf][br + 8][bc]) =
        *reinterpret_cast<const float4*>(&W[(size_t)(kk + br + 8) * N + bn + bc]);
}

__device__ __forceinline__
void gemm_body(const float* __restrict__ A, const float* __restrict__ W,
               const float* __restrict__ bias, float* __restrict__ out,
               int M, int N, int K, int act, int bm, int bn)
{
    __shared__ GemmSmem s;

    const int tid = threadIdx.x;
    const int tx = tid & 15;       // 0..15  -> column group
    const int ty = tid >> 4;       // 0..15  -> row group

    // A-tile load mapping: 64 rows/pass x 4 float4 columns
    const int ar = tid >> 2;              // 0..63
    const int ac = (tid & 3) * 4;         // 0,4,8,12
    // B-tile load mapping: 8 rows/pass x 32 float4 columns
    const int br = tid >> 5;              // 0..7
    const int bc = (tid & 31) * 4;        // 0..124

    float2 acc[TM][TN/2];
    #pragma unroll
    for (int i = 0; i < TM; i++)
        #pragma unroll
        for (int j = 0; j < TN/2; j++) acc[i][j] = make_float2(0.f, 0.f);

    gemm_load_tile(s, 0, A, W, bm, bn, 0, K, N, ar, ac, br, bc);
    __syncthreads();

    int buf = 0;
    for (int kk = 0; kk < K; kk += BK, buf ^= 1) {
        if (kk + BK < K)
            gemm_load_tile(s, buf ^ 1, A, W, bm, bn, kk + BK, K, N, ar, ac, br, bc);

        #pragma unroll
        for (int k = 0; k < BK; k++) {
            float4 m0 = *reinterpret_cast<const float4*>(&s.As[buf][k][ty * TM]);
            float4 m1 = *reinterpret_cast<const float4*>(&s.As[buf][k][ty * TM + 4]);
            float4 n0 = *reinterpret_cast<const float4*>(&s.Bs[buf][k][tx * TN]);
            float4 n1 = *reinterpret_cast<const float4*>(&s.Bs[buf][k][tx * TN + 4]);
            float rm[TM] = {m0.x, m0.y, m0.z, m0.w, m1.x, m1.y, m1.z, m1.w};
            float2 rn[TN/2] = {make_float2(n0.x, n0.y), make_float2(n0.z, n0.w),
                               make_float2(n1.x, n1.y), make_float2(n1.z, n1.w)};
            #pragma unroll
            for (int i = 0; i < TM; i++) {
                float2 ai = make_float2(rm[i], rm[i]);
                #pragma unroll
                for (int j = 0; j < TN/2; j++)
                    acc[i][j] = ffma2(ai, rn[j], acc[i][j]);
            }
        }
        __syncthreads();
    }

    // epilogue
    #pragma unroll
    for (int i = 0; i < TM; i++) {
        int row = bm + ty * TM + i;
        #pragma unroll
        for (int j = 0; j < TN/2; j++) {
            int col = bn + tx * TN + j * 2;
            float2 v = acc[i][j];
            v.x += bias[col];
            v.y += bias[col + 1];
            if (act == 1) { v.x = act_sigmoid(v.x);  v.y = act_sigmoid(v.y); }
            else if (act == 2) { v.x = act_softplus(v.x); v.y = act_softplus(v.y); }
            *reinterpret_cast<float2*>(&out[(size_t)row * N + col]) = v;
        }
    }
}

// Fused input projections: z = sigmoid(x@Wz+bz), x_ssm = x@Wx+bx, dt = softplus(x@Wdt+bdt)
// grid: (3 * DD/BN, MROWS/BM). blockIdx.x / 8 selects which projection.
__global__ __launch_bounds__(256)
void sgemm_fused3(const float* __restrict__ x,
                  const float* __restrict__ Wz,  const float* __restrict__ bz,
                  const float* __restrict__ Wx,  const float* __restrict__ bx,
                  const float* __restrict__ Wdt, const float* __restrict__ bdt,
                  float* __restrict__ oz, float* __restrict__ ox, float* __restrict__ odt)
{
    const int which = blockIdx.x >> 3;
    const int bn = (blockIdx.x & 7) * BN;
    const int bm = blockIdx.y * BM;
    const float* W;  const float* bias;  float* out;  int act;
    if (which == 0)      { W = Wz;  bias = bz;  out = oz;  act = 1; }
    else if (which == 1) { W = Wx;  bias = bx;  out = ox;  act = 0; }
    else                 { W = Wdt; bias = bdt; out = odt; act = 2; }
    gemm_body(x, W, bias, out, MROWS, DD, DD, act, bm, bn);
}

// Single GEMM (output projection)
__global__ __launch_bounds__(256)
void sgemm_act(const float* __restrict__ A, const float* __restrict__ W,
               const float* __restrict__ bias, float* __restrict__ out)
{
    gemm_body(A, W, bias, out, MROWS, DD, DD, 0,
              blockIdx.y * BM, blockIdx.x * BN);
}

// ---------------- small projections: Bm = x@WB+bB, C = x@WC+bC ----------------
// one block handles 16 rows; 256 threads = 16 rows x 16 state cols
__global__ __launch_bounds__(256)
void small_proj(const float* __restrict__ x,
                const float* __restrict__ WB, const float* __restrict__ bB,
                const float* __restrict__ WC, const float* __restrict__ bC)
{
    __shared__ float xs[16][64];
    __shared__ float wbs[64][NST];
    __shared__ float wcs[64][NST];

    const int tid = threadIdx.x;
    const int rb = blockIdx.x * 16;
    const int r = tid >> 4;
    const int n = tid & 15;

    float accB = 0.f, accC = 0.f;
    for (int kk = 0; kk < DD; kk += 64) {
        __syncthreads();
        #pragma unroll
        for (int s = 0; s < 4; s++) {
            int idx = tid + s * 256;            // 0..1023
            xs[idx >> 6][idx & 63] = x[(size_t)(rb + (idx >> 6)) * DD + kk + (idx & 63)];
            wbs[idx >> 4][idx & 15] = WB[(size_t)(kk + (idx >> 4)) * NST + (idx & 15)];
            wcs[idx >> 4][idx & 15] = WC[(size_t)(kk + (idx >> 4)) * NST + (idx & 15)];
        }
        __syncthreads();
        #pragma unroll
        for (int k = 0; k < 64; k++) {
            float xv = xs[r][k];
            accB = fmaf(xv, wbs[k][n], accB);
            accC = fmaf(xv, wcs[k][n], accC);
        }
    }
    g_Bm[(size_t)(rb + r) * NST + n] = accB + bB[n];
    g_Cc[(size_t)(rb + r) * NST + n] = accC + bC[n];
}

// ---------------- SSM scan, chunked (exact reassociation) ----------------
// phase A: per (b, chunk, d): local scan with h0=0; store h_end and prod(a)
__global__ __launch_bounds__(256)
void scan_phaseA(const float* __restrict__ A_log)
{
    const int gid = blockIdx.x * blockDim.x + threadIdx.x;   // 65536
    const int d = gid % DD;
    const int c = (gid / DD) % NCHUNK;
    const int b = gid / (DD * NCHUNK);

    float Ad[NST];
    #pragma unroll
    for (int n = 0; n < NST; n++) Ad[n] = -__expf(A_log[(size_t)d * NST + n]);

    float h[NST], P[NST];
    #pragma unroll
    for (int n = 0; n < NST; n++) { h[n] = 0.f; P[n] = 1.f; }

    const int l0 = c * CLEN;
    const float* dtp = g_dt + ((size_t)b * LSEQ + l0) * DD + d;
    const float* xp  = g_xs + ((size_t)b * LSEQ + l0) * DD + d;
    const float* Bp  = g_Bm + ((size_t)b * LSEQ + l0) * NST;

    for (int s = 0; s < CLEN; s++) {
        float dtv = dtp[(size_t)s * DD];
        float xv  = xp[(size_t)s * DD];
        float xb  = xv * dtv;
        float4 b0 = *reinterpret_cast<const float4*>(Bp + (size_t)s * NST + 0);
        float4 b1 = *reinterpret_cast<const float4*>(Bp + (size_t)s * NST + 4);
        float4 b2 = *reinterpret_cast<const float4*>(Bp + (size_t)s * NST + 8);
        float4 b3 = *reinterpret_cast<const float4*>(Bp + (size_t)s * NST + 12);
        float Bl[NST] = {b0.x,b0.y,b0.z,b0.w, b1.x,b1.y,b1.z,b1.w,
                         b2.x,b2.y,b2.z,b2.w, b3.x,b3.y,b3.z,b3.w};
        #pragma unroll
        for (int n = 0; n < NST; n++) {
            float a = __expf(dtv * Ad[n]);
            h[n] = fmaf(a, h[n], xb * Bl[n]);
            P[n] *= a;
        }
    }
    const size_t base = ((size_t)(b * DD + d) * NCHUNK + c) * NST;
    #pragma unroll
    for (int q = 0; q < 4; q++) {
        *reinterpret_cast<float4*>(&g_hend[base + q * 4]) =
            make_float4(h[q*4], h[q*4+1], h[q*4+2], h[q*4+3]);
        *reinterpret_cast<float4*>(&g_P[base + q * 4]) =
            make_float4(P[q*4], P[q*4+1], P[q*4+2], P[q*4+3]);
    }
}

// phase B: per (b,d,n): compose 32 chunk maps -> h_start per chunk
__global__ __launch_bounds__(256)
void scan_phaseB()
{
    const int gid = blockIdx.x * blockDim.x + threadIdx.x;   // 32768
    const int n = gid & 15;
    const int bd = gid >> 4;
    float carry = 0.f;
    #pragma unroll
    for (int c = 0; c < NCHUNK; c++) {
        size_t idx = ((size_t)bd * NCHUNK + c) * NST + n;
        g_hs[idx] = carry;
        carry = fmaf(g_P[idx], carry, g_hend[idx]);
    }
}

// phase C: re-run chunk from correct h_start, emit u = (h . C) * z
__global__ __launch_bounds__(256)
void scan_phaseC(const float* __restrict__ A_log)
{
    const int gid = blockIdx.x * blockDim.x + threadIdx.x;   // 65536
    const int d = gid % DD;
    const int c = (gid / DD) % NCHUNK;
    const int b = gid / (DD * NCHUNK);

    float Ad[NST];
    #pragma unroll
    for (int n = 0; n < NST; n++) Ad[n] = -__expf(A_log[(size_t)d * NST + n]);

    float h[NST];
    const size_t hbase = ((size_t)(b * DD + d) * NCHUNK + c) * NST;
    #pragma unroll
    for (int q = 0; q < 4; q++) {
        float4 hv = *reinterpret_cast<const float4*>(&g_hs[hbase + q * 4]);
        h[q*4] = hv.x; h[q*4+1] = hv.y; h[q*4+2] = hv.z; h[q*4+3] = hv.w;
    }

    const int l0 = c * CLEN;
    const float* dtp = g_dt + ((size_t)b * LSEQ + l0) * DD + d;
    const float* xp  = g_xs + ((size_t)b * LSEQ + l0) * DD + d;
    const float* zp  = g_z  + ((size_t)b * LSEQ + l0) * DD + d;
    const float* Bp  = g_Bm + ((size_t)b * LSEQ + l0) * NST;
    const float* Cp  = g_Cc + ((size_t)b * LSEQ + l0) * NST;
    float* up = g_u + ((size_t)b * LSEQ + l0) * DD + d;

    for (int s = 0; s < CLEN; s++) {
        float dtv = dtp[(size_t)s * DD];
        float xv  = xp[(size_t)s * DD];
        float xb  = xv * dtv;
        float4 b0 = *reinterpret_cast<const float4*>(Bp + (size_t)s * NST + 0);
        float4 b1 = *reinterpret_cast<const float4*>(Bp + (size_t)s * NST + 4);
        float4 b2 = *reinterpret_cast<const float4*>(Bp + (size_t)s * NST + 8);
        float4 b3 = *reinterpret_cast<const float4*>(Bp + (size_t)s * NST + 12);
        float4 c0 = *reinterpret_cast<const float4*>(Cp + (size_t)s * NST + 0);
        float4 c1 = *reinterpret_cast<const float4*>(Cp + (size_t)s * NST + 4);
        float4 c2 = *reinterpret_cast<const float4*>(Cp + (size_t)s * NST + 8);
        float4 c3 = *reinterpret_cast<const float4*>(Cp + (size_t)s * NST + 12);
        float Bl[NST] = {b0.x,b0.y,b0.z,b0.w, b1.x,b1.y,b1.z,b1.w,
                         b2.x,b2.y,b2.z,b2.w, b3.x,b3.y,b3.z,b3.w};
        float Cl[NST] = {c0.x,c0.y,c0.z,c0.w, c1.x,c1.y,c1.z,c1.w,
                         c2.x,c2.y,c2.z,c2.w, c3.x,c3.y,c3.z,c3.w};
        float y = 0.f;
        #pragma unroll
        for (int n = 0; n < NST; n++) {
            float a = __expf(dtv * Ad[n]);
            h[n] = fmaf(a, h[n], xb * Bl[n]);
            y = fmaf(h[n], Cl[n], y);
        }
        up[(size_t)s * DD] = y * zp[(size_t)s * DD];
    }
}

// ---------------- launch ----------------
extern "C" void kernel_launch(void* const* d_in, const int* in_sizes, int n_in,
                              void* d_out, int out_size)
{
    const float* x     = (const float*)d_in[0];
    const float* Wz    = (const float*)d_in[1];
    const float* bz    = (const float*)d_in[2];
    const float* Wx    = (const float*)d_in[3];
    const float* bx    = (const float*)d_in[4];
    const float* WB    = (const float*)d_in[5];
    const float* bB    = (const float*)d_in[6];
    const float* WC    = (const float*)d_in[7];
    const float* bC    = (const float*)d_in[8];
    const float* Wdt   = (const float*)d_in[9];
    const float* bdt   = (const float*)d_in[10];
    const float* A_log = (const float*)d_in[11];
    const float* Wout  = (const float*)d_in[12];
    const float* bout  = (const float*)d_in[13];
    float* out = (float*)d_out;

    float *pz, *pxs, *pdt, *pu;
    cudaGetSymbolAddress((void**)&pz,  g_z);
    cudaGetSymbolAddress((void**)&pxs, g_xs);
    cudaGetSymbolAddress((void**)&pdt, g_dt);
    cudaGetSymbolAddress((void**)&pu,  g_u);

    dim3 fused_grid(3 * DD / BN, MROWS / BM);   // (24, 32)
    sgemm_fused3<<<fused_grid, 256>>>(x, Wz, bz, Wx, bx, Wdt, bdt, pz, pxs, pdt);
    small_proj<<<MROWS / 16, 256>>>(x, WB, bB, WC, bC);

    scan_phaseA<<<(BSZ * NCHUNK * DD) / 256, 256>>>(A_log);
    scan_phaseB<<<(BSZ * DD * NST) / 256, 256>>>();
    scan_phaseC<<<(BSZ * NCHUNK * DD) / 256, 256>>>(A_log);

    dim3 gemm_grid(DD / BN, MROWS / BM);        // (8, 32)
    sgemm_act<<<gemm_grid, 256>>>(pu, Wout, bout, out);
}

// round 14
// speedup vs baseline: 1.6753x; 1.6753x over previous
#include <cuda_runtime.h>
#include <cuda_bf16.h>
#include <cstdint>

// Problem shapes (fixed by the dataset)
#define DD   1024
#define BSZ  2
#define LSEQ 2048
#define NST  16
#define MROWS (BSZ*LSEQ)      // 4096
#define NCHUNK 32
#define CLEN  (LSEQ/NCHUNK)   // 64

// HMMA GEMM config: 128x128 CTA tile, BK=32 chunks, double-buffered cp.async
#define BKC   32
#define GKCH  (DD/BKC)        // 32 chunks
#define ASTR  40              // smem row stride in bf16 (pad: conflict-free ldmatrix)
#define MAT_BYTES (128*ASTR*2)          // 10240 per matrix tile
#define BUF_BYTES (4*MAT_BYTES)         // Ah, Al, Bh, Bl
#define TC_SMEM   (2*BUF_BYTES)         // 81920 double-buffered

// ---------------- scratch (no allocs allowed) ----------------
__device__ float g_z [MROWS*DD];
__device__ float g_xs[MROWS*DD];
__device__ float g_dt[MROWS*DD];
__device__ float g_Bm[MROWS*NST];
__device__ float g_Cc[MROWS*NST];
__device__ float g_hend[BSZ*DD*NCHUNK*NST];
__device__ float g_P   [BSZ*DD*NCHUNK*NST];
__device__ float g_hs  [BSZ*DD*NCHUNK*NST];
// bf16 split operands
__device__ __align__(16) __nv_bfloat16 g_xh[MROWS*DD];
__device__ __align__(16) __nv_bfloat16 g_xl[MROWS*DD];
__device__ __align__(16) __nv_bfloat16 g_uh[MROWS*DD];
__device__ __align__(16) __nv_bfloat16 g_ul[MROWS*DD];
__device__ __align__(16) __nv_bfloat16 g_Wh[4*DD*DD];   // transposed: [w][n][k]
__device__ __align__(16) __nv_bfloat16 g_Wl[4*DD*DD];

// ---------------- PTX helpers (baseline ISA only — no sm_103a features) ----------------
__device__ __forceinline__ uint32_t smem_u32(const void* p) {
    uint32_t a;
    asm("{ .reg .u64 t; cvta.to.shared.u64 t, %1; cvt.u32.u64 %0, t; }" : "=r"(a) : "l"(p));
    return a;
}
__device__ __forceinline__ void ldsm4(uint32_t* r, uint32_t addr) {
    asm volatile("ldmatrix.sync.aligned.m8n8.x4.shared.b16 {%0,%1,%2,%3}, [%4];"
        : "=r"(r[0]), "=r"(r[1]), "=r"(r[2]), "=r"(r[3]) : "r"(addr));
}
__device__ __forceinline__ void mma16816(float* c, const uint32_t* a, uint32_t b0, uint32_t b1) {
    asm volatile("mma.sync.aligned.m16n8k16.row.col.f32.bf16.bf16.f32 "
        "{%0,%1,%2,%3}, {%4,%5,%6,%7}, {%8,%9}, {%0,%1,%2,%3};"
        : "+f"(c[0]), "+f"(c[1]), "+f"(c[2]), "+f"(c[3])
        : "r"(a[0]), "r"(a[1]), "r"(a[2]), "r"(a[3]), "r"(b0), "r"(b1));
}
#define CP_ASYNC16(dst, src) \
    asm volatile("cp.async.cg.shared.global [%0], [%1], 16;" :: "r"(dst), "l"(src))
#define CP_COMMIT() asm volatile("cp.async.commit_group;" ::: "memory")

__device__ __forceinline__ float act_sigmoid(float x) { return 1.0f / (1.0f + __expf(-x)); }
__device__ __forceinline__ float act_softplus(float x) {
    return fmaxf(x, 0.0f) + log1pf(__expf(-fabsf(x)));
}

// ---------------- fp32 -> bf16 hi/lo split (elementwise, float4) ----------------
__global__ __launch_bounds__(256)
void split_fp32(const float* __restrict__ src, __nv_bfloat16* __restrict__ hi,
                __nv_bfloat16* __restrict__ lo, int n4)
{
    int i = blockIdx.x * blockDim.x + threadIdx.x;
    if (i >= n4) return;
    float4 v = reinterpret_cast<const float4*>(src)[i];
    __nv_bfloat16 h0 = __float2bfloat16(v.x), h1 = __float2bfloat16(v.y);
    __nv_bfloat16 h2 = __float2bfloat16(v.z), h3 = __float2bfloat16(v.w);
    __nv_bfloat16 l0 = __float2bfloat16(v.x - __bfloat162float(h0));
    __nv_bfloat16 l1 = __float2bfloat16(v.y - __bfloat162float(h1));
    __nv_bfloat16 l2 = __float2bfloat16(v.z - __bfloat162float(h2));
    __nv_bfloat16 l3 = __float2bfloat16(v.w - __bfloat162float(h3));
    __nv_bfloat162* H = reinterpret_cast<__nv_bfloat162*>(hi);
    __nv_bfloat162* L = reinterpret_cast<__nv_bfloat162*>(lo);
    H[2*i]   = __halves2bfloat162(h0, h1);
    H[2*i+1] = __halves2bfloat162(h2, h3);
    L[2*i]   = __halves2bfloat162(l0, l1);
    L[2*i+1] = __halves2bfloat162(l2, l3);
}

// ---------------- weight transpose + split: Wt[n][k] = W[k][n] ----------------
__global__ __launch_bounds__(1024)
void wsplit_t(const float* __restrict__ W0, const float* __restrict__ W1,
              const float* __restrict__ W2, const float* __restrict__ W3,
              __nv_bfloat16* __restrict__ H, __nv_bfloat16* __restrict__ L)
{
    __shared__ float t[32][33];
    const int w = blockIdx.z;
    const float* W = (w == 0) ? W0 : (w == 1) ? W1 : (w == 2) ? W2 : W3;
    __nv_bfloat16* th = H + (size_t)w * DD * DD;
    __nv_bfloat16* tl = L + (size_t)w * DD * DD;
    const int n0 = blockIdx.x * 32, k0 = blockIdx.y * 32;
    const int tx = threadIdx.x, ty = threadIdx.y;
    t[ty][tx] = W[(size_t)(k0 + ty) * DD + n0 + tx];
    __syncthreads();
    float v = t[tx][ty];                       // = W[k0+tx][n0+ty]
    __nv_bfloat16 h = __float2bfloat16(v);
    __nv_bfloat16 l = __float2bfloat16(v - __bfloat162float(h));
    th[(size_t)(n0 + ty) * DD + k0 + tx] = h;
    tl[(size_t)(n0 + ty) * DD + k0 + tx] = l;
}

// ---------------- HMMA GEMM body ----------------
// out[m][n] = act( sum_k A[m][k]*W[k][n] + bias[n] ); A≈Ah+Al, Wt≈Wh+Wl ([n][k] N-major)
// 256 threads = 8 warps; warp tile 64x32 (wm = wid&1, wn = wid>>1)
__device__ __forceinline__
void load_chunk(uint32_t sb, int buf,
                const __nv_bfloat16* __restrict__ Ah, const __nv_bfloat16* __restrict__ Al,
                const __nv_bfloat16* __restrict__ Bh, const __nv_bfloat16* __restrict__ Bl,
                int bm, int bn, int kk, int tid)
{
    #pragma unroll
    for (int m = 0; m < 4; m++) {
        const __nv_bfloat16* g = (m == 0) ? Ah : (m == 1) ? Al : (m == 2) ? Bh : Bl;
        const int rowbase = (m < 2) ? bm : bn;
        #pragma unroll
        for (int i = 0; i < 2; i++) {
            int q = tid + i * 256;             // 0..511
            int row = q >> 2, c16 = q & 3;
            uint32_t dst = sb + (uint32_t)(buf * BUF_BYTES + m * MAT_BYTES)
                              + (uint32_t)((row * ASTR + c16 * 8) * 2);
            const void* src = g + (size_t)(rowbase + row) * DD + kk + c16 * 8;
            CP_ASYNC16(dst, src);
        }
    }
}

__device__ void tc_gemm_body(const __nv_bfloat16* __restrict__ Ah, const __nv_bfloat16* __restrict__ Al,
                             const __nv_bfloat16* __restrict__ Wh, const __nv_bfloat16* __restrict__ Wl,
                             const float* __restrict__ bias, float* __restrict__ out,
                             int act, int bm, int bn)
{
    extern __shared__ __align__(16) char dsm[];
    const uint32_t sb = smem_u32(dsm);
    const int tid = threadIdx.x;
    const int lane = tid & 31;
    const int wid = tid >> 5;
    const int wm = wid & 1;        // 0..1 (64 rows each)
    const int wn = wid >> 1;       // 0..3 (32 cols each)

    // ldmatrix lane addressing
    const int a_r  = lane & 15;              // row within m16
    const int a_c8 = ((lane >> 4) & 1) * 8;  // k-half select
    const int b_r  = (lane & 7) + ((lane >> 3) & 1) * 8;  // n within n16
    const int b_c8 = (lane >> 4) * 8;

    float acc[4][4][4];
    #pragma unroll
    for (int i = 0; i < 4; i++)
        #pragma unroll
        for (int j = 0; j < 4; j++)
            #pragma unroll
            for (int r = 0; r < 4; r++) acc[i][j][r] = 0.f;

    load_chunk(sb, 0, Ah, Al, Wh, Wl, bm, bn, 0, tid);
    CP_COMMIT();

    #pragma unroll 1
    for (int c = 0; c < GKCH; c++) {
        if (c + 1 < GKCH) {
            load_chunk(sb, (c + 1) & 1, Ah, Al, Wh, Wl, bm, bn, (c + 1) * BKC, tid);
            CP_COMMIT();
            asm volatile("cp.async.wait_group 1;" ::: "memory");
        } else {
            asm volatile("cp.async.wait_group 0;" ::: "memory");
        }
        __syncthreads();

        const uint32_t mb = sb + (uint32_t)((c & 1) * BUF_BYTES);
        #pragma unroll
        for (int ks = 0; ks < 2; ks++) {
            uint32_t bh[2][4], bl[2][4];
            #pragma unroll
            for (int nb = 0; nb < 2; nb++) {
                uint32_t off = (uint32_t)(((wn * 32 + nb * 16 + b_r) * ASTR + ks * 16 + b_c8) * 2);
                ldsm4(bh[nb], mb + 2 * MAT_BYTES + off);
                ldsm4(bl[nb], mb + 3 * MAT_BYTES + off);
            }
            #pragma unroll
            for (int mf = 0; mf < 4; mf++) {
                uint32_t aoff = (uint32_t)(((wm * 64 + mf * 16 + a_r) * ASTR + ks * 16 + a_c8) * 2);
                uint32_t ahr[4], alr[4];
                ldsm4(ahr, mb + 0 * MAT_BYTES + aoff);
                ldsm4(alr, mb + 1 * MAT_BYTES + aoff);
                #pragma unroll
                for (int nb = 0; nb < 2; nb++)
                    #pragma unroll
                    for (int h = 0; h < 2; h++) {
                        float* C = acc[mf][nb * 2 + h];
                        mma16816(C, ahr, bh[nb][h], bh[nb][2 + h]);
                        mma16816(C, ahr, bl[nb][h], bl[nb][2 + h]);
                        mma16816(C, alr, bh[nb][h], bh[nb][2 + h]);
                    }
            }
        }
        __syncthreads();
    }

    // epilogue: bias + act, fp32 stores (float2 per frag half)
    const int r_in = lane >> 2;
    const int c_in = (lane & 3) * 2;
    #pragma unroll
    for (int mf = 0; mf < 4; mf++) {
        const int row = bm + wm * 64 + mf * 16 + r_in;
        #pragma unroll
        for (int nf = 0; nf < 4; nf++) {
            const int col = bn + wn * 32 + nf * 8 + c_in;
            const float b0 = __ldg(&bias[col]), b1 = __ldg(&bias[col + 1]);
            float2 v0 = make_float2(acc[mf][nf][0] + b0, acc[mf][nf][1] + b1);
            float2 v1 = make_float2(acc[mf][nf][2] + b0, acc[mf][nf][3] + b1);
            if (act == 1) {
                v0.x = act_sigmoid(v0.x); v0.y = act_sigmoid(v0.y);
                v1.x = act_sigmoid(v1.x); v1.y = act_sigmoid(v1.y);
            } else if (act == 2) {
                v0.x = act_softplus(v0.x); v0.y = act_softplus(v0.y);
                v1.x = act_softplus(v1.x); v1.y = act_softplus(v1.y);
            }
            *reinterpret_cast<float2*>(&out[(size_t)row * DD + col]) = v0;
            *reinterpret_cast<float2*>(&out[(size_t)(row + 8) * DD + col]) = v1;
        }
    }
}

// fused input projections (z: sigmoid, x_ssm: none, dt: softplus)
__global__ __launch_bounds__(256, 2)
void tc_gemm_fused3(const __nv_bfloat16* __restrict__ xh, const __nv_bfloat16* __restrict__ xl,
                    const __nv_bfloat16* __restrict__ WH, const __nv_bfloat16* __restrict__ WL,
                    const float* __restrict__ bz, const float* __restrict__ bx,
                    const float* __restrict__ bdt,
                    float* __restrict__ oz, float* __restrict__ ox, float* __restrict__ odt)
{
    const int w = blockIdx.z;
    const float* bias; float* out; int act;
    if (w == 0)      { bias = bz;  out = oz;  act = 1; }
    else if (w == 1) { bias = bx;  out = ox;  act = 0; }
    else             { bias = bdt; out = odt; act = 2; }
    tc_gemm_body(xh, xl, WH + (size_t)w * DD * DD, WL + (size_t)w * DD * DD,
                 bias, out, act, blockIdx.y * 128, blockIdx.x * 128);
}

__global__ __launch_bounds__(256, 2)
void tc_gemm_out(const __nv_bfloat16* __restrict__ uh, const __nv_bfloat16* __restrict__ ul,
                 const __nv_bfloat16* __restrict__ Wh, const __nv_bfloat16* __restrict__ Wl,
                 const float* __restrict__ bias, float* __restrict__ out)
{
    tc_gemm_body(uh, ul, Wh, Wl, bias, out, 0, blockIdx.y * 128, blockIdx.x * 128);
}

// ---------------- small projections: Bm = x@WB+bB, C = x@WC+bC ----------------
__global__ __launch_bounds__(256)
void small_proj(const float* __restrict__ x,
                const float* __restrict__ WB, const float* __restrict__ bB,
                const float* __restrict__ WC, const float* __restrict__ bC)
{
    __shared__ float xs[16][64];
    __shared__ float wbs[64][NST];
    __shared__ float wcs[64][NST];

    const int tid = threadIdx.x;
    const int rb = blockIdx.x * 16;
    const int r = tid >> 4;
    const int n = tid & 15;

    float accB = 0.f, accC = 0.f;
    for (int kk = 0; kk < DD; kk += 64) {
        __syncthreads();
        #pragma unroll
        for (int s = 0; s < 4; s++) {
            int idx = tid + s * 256;
            xs[idx >> 6][idx & 63] = x[(size_t)(rb + (idx >> 6)) * DD + kk + (idx & 63)];
            wbs[idx >> 4][idx & 15] = WB[(size_t)(kk + (idx >> 4)) * NST + (idx & 15)];
            wcs[idx >> 4][idx & 15] = WC[(size_t)(kk + (idx >> 4)) * NST + (idx & 15)];
        }
        __syncthreads();
        #pragma unroll
        for (int k = 0; k < 64; k++) {
            float xv = xs[r][k];
            accB = fmaf(xv, wbs[k][n], accB);
            accC = fmaf(xv, wcs[k][n], accC);
        }
    }
    g_Bm[(size_t)(rb + r) * NST + n] = accB + bB[n];
    g_Cc[(size_t)(rb + r) * NST + n] = accC + bC[n];
}

// ---------------- SSM scan, chunked (exact reassociation) ----------------
__global__ __launch_bounds__(256)
void scan_phaseA(const float* __restrict__ A_log)
{
    const int gid = blockIdx.x * blockDim.x + threadIdx.x;
    const int d = gid % DD;
    const int c = (gid / DD) % NCHUNK;
    const int b = gid / (DD * NCHUNK);

    float Ad[NST];
    #pragma unroll
    for (int n = 0; n < NST; n++) Ad[n] = -__expf(A_log[(size_t)d * NST + n]);

    float h[NST], P[NST];
    #pragma unroll
    for (int n = 0; n < NST; n++) { h[n] = 0.f; P[n] = 1.f; }

    const int l0 = c * CLEN;
    const float* dtp = g_dt + ((size_t)b * LSEQ + l0) * DD + d;
    const float* xp  = g_xs + ((size_t)b * LSEQ + l0) * DD + d;
    const float* Bp  = g_Bm + ((size_t)b * LSEQ + l0) * NST;

    for (int s = 0; s < CLEN; s++) {
        float dtv = dtp[(size_t)s * DD];
        float xv  = xp[(size_t)s * DD];
        float xb  = xv * dtv;
        float4 b0 = *reinterpret_cast<const float4*>(Bp + (size_t)s * NST + 0);
        float4 b1 = *reinterpret_cast<const float4*>(Bp + (size_t)s * NST + 4);
        float4 b2 = *reinterpret_cast<const float4*>(Bp + (size_t)s * NST + 8);
        float4 b3 = *reinterpret_cast<const float4*>(Bp + (size_t)s * NST + 12);
        float Bl[NST] = {b0.x,b0.y,b0.z,b0.w, b1.x,b1.y,b1.z,b1.w,
                         b2.x,b2.y,b2.z,b2.w, b3.x,b3.y,b3.z,b3.w};
        #pragma unroll
        for (int n = 0; n < NST; n++) {
            float a = __expf(dtv * Ad[n]);
            h[n] = fmaf(a, h[n], xb * Bl[n]);
            P[n] *= a;
        }
    }
    const size_t base = ((size_t)(b * DD + d) * NCHUNK + c) * NST;
    #pragma unroll
    for (int q = 0; q < 4; q++) {
        *reinterpret_cast<float4*>(&g_hend[base + q * 4]) =
            make_float4(h[q*4], h[q*4+1], h[q*4+2], h[q*4+3]);
        *reinterpret_cast<float4*>(&g_P[base + q * 4]) =
            make_float4(P[q*4], P[q*4+1], P[q*4+2], P[q*4+3]);
    }
}

__global__ __launch_bounds__(256)
void scan_phaseB()
{
    const int gid = blockIdx.x * blockDim.x + threadIdx.x;
    const int n = gid & 15;
    const int bd = gid >> 4;
    float carry = 0.f;
    #pragma unroll
    for (int c = 0; c < NCHUNK; c++) {
        size_t idx = ((size_t)bd * NCHUNK + c) * NST + n;
        g_hs[idx] = carry;
        carry = fmaf(g_P[idx], carry, g_hend[idx]);
    }
}

// phase C: re-run chunk from correct h_start; emit u = (h.C)*z directly as bf16 hi/lo
__global__ __launch_bounds__(256)
void scan_phaseC(const float* __restrict__ A_log)
{
    const int gid = blockIdx.x * blockDim.x + threadIdx.x;
    const int d = gid % DD;
    const int c = (gid / DD) % NCHUNK;
    const int b = gid / (DD * NCHUNK);

    float Ad[NST];
    #pragma unroll
    for (int n = 0; n < NST; n++) Ad[n] = -__expf(A_log[(size_t)d * NST + n]);

    float h[NST];
    const size_t hbase = ((size_t)(b * DD + d) * NCHUNK + c) * NST;
    #pragma unroll
    for (int q = 0; q < 4; q++) {
        float4 hv = *reinterpret_cast<const float4*>(&g_hs[hbase + q * 4]);
        h[q*4] = hv.x; h[q*4+1] = hv.y; h[q*4+2] = hv.z; h[q*4+3] = hv.w;
    }

    const int l0 = c * CLEN;
    const float* dtp = g_dt + ((size_t)b * LSEQ + l0) * DD + d;
    const float* xp  = g_xs + ((size_t)b * LSEQ + l0) * DD + d;
    const float* zp  = g_z  + ((size_t)b * LSEQ + l0) * DD + d;
    const float* Bp  = g_Bm + ((size_t)b * LSEQ + l0) * NST;
    const float* Cp  = g_Cc + ((size_t)b * LSEQ + l0) * NST;
    __nv_bfloat16* uhp = g_uh + ((size_t)b * LSEQ + l0) * DD + d;
    __nv_bfloat16* ulp = g_ul + ((size_t)b * LSEQ + l0) * DD + d;

    for (int s = 0; s < CLEN; s++) {
        float dtv = dtp[(size_t)s * DD];
        float xv  = xp[(size_t)s * DD];
        float xb  = xv * dtv;
        float4 b0 = *reinterpret_cast<const float4*>(Bp + (size_t)s * NST + 0);
        float4 b1 = *reinterpret_cast<const float4*>(Bp + (size_t)s * NST + 4);
        float4 b2 = *reinterpret_cast<const float4*>(Bp + (size_t)s * NST + 8);
        float4 b3 = *reinterpret_cast<const float4*>(Bp + (size_t)s * NST + 12);
        float4 c0 = *reinterpret_cast<const float4*>(Cp + (size_t)s * NST + 0);
        float4 c1 = *reinterpret_cast<const float4*>(Cp + (size_t)s * NST + 4);
        float4 c2 = *reinterpret_cast<const float4*>(Cp + (size_t)s * NST + 8);
        float4 c3 = *reinterpret_cast<const float4*>(Cp + (size_t)s * NST + 12);
        float Bl[NST] = {b0.x,b0.y,b0.z,b0.w, b1.x,b1.y,b1.z,b1.w,
                         b2.x,b2.y,b2.z,b2.w, b3.x,b3.y,b3.z,b3.w};
        float Cl[NST] = {c0.x,c0.y,c0.z,c0.w, c1.x,c1.y,c1.z,c1.w,
                         c2.x,c2.y,c2.z,c2.w, c3.x,c3.y,c3.z,c3.w};
        float y = 0.f;
        #pragma unroll
        for (int n = 0; n < NST; n++) {
            float a = __expf(dtv * Ad[n]);
            h[n] = fmaf(a, h[n], xb * Bl[n]);
            y = fmaf(h[n], Cl[n], y);
        }
        float v = y * zp[(size_t)s * DD];
        __nv_bfloat16 vh = __float2bfloat16(v);
        uhp[(size_t)s * DD] = vh;
        ulp[(size_t)s * DD] = __float2bfloat16(v - __bfloat162float(vh));
    }
}

// ---------------- launch ----------------
extern "C" void kernel_launch(void* const* d_in, const int* in_sizes, int n_in,
                              void* d_out, int out_size)
{
    const float* x     = (const float*)d_in[0];
    const float* Wz    = (const float*)d_in[1];
    const float* bz    = (const float*)d_in[2];
    const float* Wx    = (const float*)d_in[3];
    const float* bx    = (const float*)d_in[4];
    const float* WB    = (const float*)d_in[5];
    const float* bB    = (const float*)d_in[6];
    const float* WC    = (const float*)d_in[7];
    const float* bC    = (const float*)d_in[8];
    const float* Wdt   = (const float*)d_in[9];
    const float* bdt   = (const float*)d_in[10];
    const float* A_log = (const float*)d_in[11];
    const float* Wout  = (const float*)d_in[12];
    const float* bout  = (const float*)d_in[13];
    float* out = (float*)d_out;

    float *pz, *pxs, *pdt;
    __nv_bfloat16 *pxh, *pxl, *puh, *pul, *pWh, *pWl;
    cudaGetSymbolAddress((void**)&pz,  g_z);
    cudaGetSymbolAddress((void**)&pxs, g_xs);
    cudaGetSymbolAddress((void**)&pdt, g_dt);
    cudaGetSymbolAddress((void**)&pxh, g_xh);
    cudaGetSymbolAddress((void**)&pxl, g_xl);
    cudaGetSymbolAddress((void**)&puh, g_uh);
    cudaGetSymbolAddress((void**)&pul, g_ul);
    cudaGetSymbolAddress((void**)&pWh, g_Wh);
    cudaGetSymbolAddress((void**)&pWl, g_Wl);

    cudaFuncSetAttribute(tc_gemm_fused3, cudaFuncAttributeMaxDynamicSharedMemorySize, TC_SMEM);
    cudaFuncSetAttribute(tc_gemm_out,    cudaFuncAttributeMaxDynamicSharedMemorySize, TC_SMEM);

    const int n4 = MROWS * DD / 4;
    split_fp32<<<n4 / 256, 256>>>(x, pxh, pxl, n4);
    wsplit_t<<<dim3(32, 32, 4), dim3(32, 32)>>>(Wz, Wx, Wdt, Wout, pWh, pWl);

    tc_gemm_fused3<<<dim3(8, 32, 3), 256, TC_SMEM>>>(pxh, pxl, pWh, pWl,
                                                     bz, bx, bdt, pz, pxs, pdt);
    small_proj<<<MROWS / 16, 256>>>(x, WB, bB, WC, bC);

    scan_phaseA<<<(BSZ * NCHUNK * DD) / 256, 256>>>(A_log);
    scan_phaseB<<<(BSZ * DD * NST) / 256, 256>>>();
    scan_phaseC<<<(BSZ * NCHUNK * DD) / 256, 256>>>(A_log);

    tc_gemm_out<<<dim3(8, 32), 256, TC_SMEM>>>(puh, pul, pWh + 3 * (size_t)DD * DD,
                                               pWl + 3 * (size_t)DD * DD, bout, out);
}